// round 2
// baseline (speedup 1.0000x reference)
#include <cuda_runtime.h>

// SlidingWindow: k,v (1, 2048, 16, 64) fp32, W=64
// out = concat(k_win, v_win), each (1, 2048, 16, 64, 64) fp32 layout [t][h][w][d]
// out_k[t,h,w,d] = (w < min(t+1,W)) ? k[max(0,t+1-W)+w, h, d] : 0

#define H_DIM 16
#define W_DIM 64

// per-tensor float4 count: 2048*16*64*64/4 = 33,554,432
#define N4 33554432LL

__global__ __launch_bounds__(256) void sliding_window_kernel(
    const float4* __restrict__ k4,
    const float4* __restrict__ v4,
    float4* __restrict__ out4)   // [0, N4) = k_win, [N4, 2N4) = v_win
{
    // each thread handles 4 consecutive float4 (64B) per tensor.
    // base is a multiple of 4, and d4 width is 16, so the 4 elements never
    // cross a w boundary -> single (t,h,w) decomposition per thread.
    const long long base = (((long long)blockIdx.x * 256) + threadIdx.x) * 4;

    const int d4 = (int)(base & 15);          // in {0,4,8,12}
    const int w  = (int)((base >> 4) & 63);
    const int h  = (int)((base >> 10) & 15);
    const int t  = (int)(base >> 14);

    const bool valid = (t >= W_DIM - 1) || (w <= t);
    const int  start = (t >= W_DIM - 1) ? (t + 1 - W_DIM) : 0;
    const long long src = (((long long)(start + w) * H_DIM + h) << 4) + d4;

    float4 kk[4], vv[4];
    if (valid) {
#pragma unroll
        for (int j = 0; j < 4; j++) {
            kk[j] = __ldg(&k4[src + j]);
            vv[j] = __ldg(&v4[src + j]);
        }
    } else {
        const float4 z = make_float4(0.f, 0.f, 0.f, 0.f);
#pragma unroll
        for (int j = 0; j < 4; j++) { kk[j] = z; vv[j] = z; }
    }

#pragma unroll
    for (int j = 0; j < 4; j++) {
        __stcs(&out4[base + j],      kk[j]);   // evict-first: write-once stream
        __stcs(&out4[base + N4 + j], vv[j]);
    }
}

extern "C" void kernel_launch(void* const* d_in, const int* in_sizes, int n_in,
                              void* d_out, int out_size) {
    const float4* k4 = (const float4*)d_in[0];
    const float4* v4 = (const float4*)d_in[1];
    float4* out4 = (float4*)d_out;

    const int threads = 256;
    const int blocks = (int)(N4 / (threads * 4));  // 32768
    sliding_window_kernel<<<blocks, threads>>>(k4, v4, out4);
}

// round 3
// speedup vs baseline: 2.3111x; 2.3111x over previous
#include <cuda_runtime.h>

// SlidingWindow: k,v (1, 2048, 16, 64) fp32, W=64
// out = concat(k_win, v_win), each (1, 2048, 16, 64, 64) fp32 layout [t][h][w][d]
// out_k[t,h,w,d] = (w < min(t+1,W)) ? k[max(0,t+1-W)+w, h, d] : 0

#define H_DIM 16
#define W_DIM 64

// per-tensor float4 count: 2048*16*64*64/4 = 33,554,432
#define N4 33554432LL

#define TPB 256
#define ILP 4

__global__ __launch_bounds__(TPB) void sliding_window_kernel(
    const float4* __restrict__ k4,
    const float4* __restrict__ v4,
    float4* __restrict__ out4)   // [0, N4) = k_win, [N4, 2N4) = v_win
{
    // Block handles TPB*ILP consecutive float4s; thread tid takes
    // tid, tid+TPB, tid+2*TPB, tid+3*TPB -> every STG instruction is a
    // fully-coalesced 512B warp transaction, with 8 independent LDGs in
    // flight per thread for MLP.
    const long long blk = (long long)blockIdx.x * (TPB * ILP) + threadIdx.x;

    long long idx[ILP];
    long long src[ILP];
    bool      valid[ILP];

#pragma unroll
    for (int j = 0; j < ILP; j++) {
        const long long i = blk + (long long)j * TPB;
        idx[j] = i;
        const int d4 = (int)(i & 15);
        const int w  = (int)((i >> 4) & 63);
        const int h  = (int)((i >> 10) & 15);
        const int t  = (int)(i >> 14);
        valid[j] = (t >= W_DIM - 1) || (w <= t);
        const int start = (t >= W_DIM - 1) ? (t + 1 - W_DIM) : 0;
        src[j] = (((long long)(start + w) * H_DIM + h) << 4) + d4;
    }

    const float4 z = make_float4(0.f, 0.f, 0.f, 0.f);
    float4 kk[ILP], vv[ILP];

    // batch all loads first -> maximum loads-in-flight
#pragma unroll
    for (int j = 0; j < ILP; j++)
        kk[j] = valid[j] ? __ldg(&k4[src[j]]) : z;
#pragma unroll
    for (int j = 0; j < ILP; j++)
        vv[j] = valid[j] ? __ldg(&v4[src[j]]) : z;

#pragma unroll
    for (int j = 0; j < ILP; j++)
        __stcs(&out4[idx[j]], kk[j]);          // evict-first write-once stream
#pragma unroll
    for (int j = 0; j < ILP; j++)
        __stcs(&out4[idx[j] + N4], vv[j]);
}

extern "C" void kernel_launch(void* const* d_in, const int* in_sizes, int n_in,
                              void* d_out, int out_size) {
    const float4* k4 = (const float4*)d_in[0];
    const float4* v4 = (const float4*)d_in[1];
    float4* out4 = (float4*)d_out;

    const int blocks = (int)(N4 / (TPB * ILP));  // 32768
    sliding_window_kernel<<<blocks, TPB>>>(k4, v4, out4);
}

// round 4
// speedup vs baseline: 2.3167x; 1.0024x over previous
#include <cuda_runtime.h>

// SlidingWindow: k,v (1, 2048, 16, 64) fp32, W=64
// out = concat(k_win, v_win), each (1, 2048, 16, 64, 64) fp32 layout [t][h][w][d]
// out_k[t,h,w,d] = (w < min(t+1,W)) ? k[max(0,t+1-W)+w, h, d] : 0

#define H_DIM 16
#define W_DIM 64

// per-tensor float4 count: 2048*16*64*64/4 = 33,554,432
#define N4 33554432LL

#define TPB 256
#define ILP 8
// one t-slice = 16*64*16 = 16384 float4s = 8 blocks of TPB*ILP=2048.
// blocks with blockIdx >= 63*8 = 504 cover t >= 63 -> always valid.
#define FIRST_ALL_VALID_BLOCK 504

__global__ __launch_bounds__(TPB) void sliding_window_kernel(
    const float4* __restrict__ k4,
    const float4* __restrict__ v4,
    float4* __restrict__ out4)   // [0, N4) = k_win, [N4, 2N4) = v_win
{
    const long long blk = (long long)blockIdx.x * (TPB * ILP) + threadIdx.x;

    long long src[ILP];
    float4 kk[ILP], vv[ILP];

    if (blockIdx.x >= FIRST_ALL_VALID_BLOCK) {
        // fast path: t >= 63, window always full, no predication.
#pragma unroll
        for (int j = 0; j < ILP; j++) {
            const long long i = blk + (long long)j * TPB;
            const int d4 = (int)(i & 15);
            const int w  = (int)((i >> 4) & 63);
            const int h  = (int)((i >> 10) & 15);
            const int t  = (int)(i >> 14);
            const int src_t = t + 1 - W_DIM + w;
            src[j] = (((long long)src_t * H_DIM + h) << 4) + d4;
        }
#pragma unroll
        for (int j = 0; j < ILP; j++) kk[j] = __ldg(&k4[src[j]]);
#pragma unroll
        for (int j = 0; j < ILP; j++) vv[j] = __ldg(&v4[src[j]]);
    } else {
        // slow path: t < 63, window may be partial (zero-fill).
        const float4 z = make_float4(0.f, 0.f, 0.f, 0.f);
        bool valid[ILP];
#pragma unroll
        for (int j = 0; j < ILP; j++) {
            const long long i = blk + (long long)j * TPB;
            const int d4 = (int)(i & 15);
            const int w  = (int)((i >> 4) & 63);
            const int h  = (int)((i >> 10) & 15);
            const int t  = (int)(i >> 14);
            valid[j] = (w <= t);          // t < 63 here, start = 0
            src[j] = (((long long)w * H_DIM + h) << 4) + d4;
        }
#pragma unroll
        for (int j = 0; j < ILP; j++) kk[j] = valid[j] ? __ldg(&k4[src[j]]) : z;
#pragma unroll
        for (int j = 0; j < ILP; j++) vv[j] = valid[j] ? __ldg(&v4[src[j]]) : z;
    }

#pragma unroll
    for (int j = 0; j < ILP; j++)
        __stcs(&out4[blk + (long long)j * TPB], kk[j]);       // evict-first stream
#pragma unroll
    for (int j = 0; j < ILP; j++)
        __stcs(&out4[blk + (long long)j * TPB + N4], vv[j]);
}

extern "C" void kernel_launch(void* const* d_in, const int* in_sizes, int n_in,
                              void* d_out, int out_size) {
    const float4* k4 = (const float4*)d_in[0];
    const float4* v4 = (const float4*)d_in[1];
    float4* out4 = (float4*)d_out;

    const int blocks = (int)(N4 / (TPB * ILP));  // 16384
    sliding_window_kernel<<<blocks, TPB>>>(k4, v4, out4);
}